// round 10
// baseline (speedup 1.0000x reference)
#include <cuda_runtime.h>
#include <cstdint>

#define NMAX 100000
#define EMAX 1600000
#define KDIM 128
#define SCAN_ITEMS 1024
#define SCAN_NBLK ((NMAX + SCAN_ITEMS - 1) / SCAN_ITEMS)

// -------- scratch (no allocations allowed; referenced directly from kernels) --------
__device__ __align__(16) float g_deg[NMAX];
__device__ __align__(16) float g_dinv[NMAX];
__device__ __align__(16) int   g_cnt[NMAX];
__device__ __align__(16) int   g_cur[NMAX];
__device__ __align__(16) int   g_rowptr[NMAX + 1];
__device__ __align__(16) int   g_bsum[SCAN_NBLK];
__device__ __align__(16) int   g_boff[SCAN_NBLK + 1];
__device__ __align__(16) int   g_col[EMAX];
__device__ __align__(16) float g_val[EMAX];
__device__ __align__(16) float g_h[(size_t)NMAX * 128];
__device__ __align__(16) float g_act[(size_t)NMAX * 128];

// -------- packed f32x2 helpers (FFMA2 path, bit-exact fp32) --------
__device__ __forceinline__ unsigned long long pk2(float a) {
    unsigned long long r;
    asm("mov.b64 %0, {%1, %1};" : "=l"(r) : "f"(a));
    return r;
}
__device__ __forceinline__ void fma2(unsigned long long& d,
                                     unsigned long long a,
                                     unsigned long long b) {
    asm("fma.rn.f32x2 %0, %1, %2, %0;" : "+l"(d) : "l"(a), "l"(b));
}
__device__ __forceinline__ float2 upk(unsigned long long v) {
    float2 r;
    asm("mov.b64 {%0, %1}, %2;" : "=f"(r.x), "=f"(r.y) : "l"(v));
    return r;
}

// ---------------- degree / histogram init ----------------
__global__ void deg_init_kernel(int n) {
    int i = blockIdx.x * blockDim.x + threadIdx.x;
    if (i < n) { g_deg[i] = 1.0f; g_cnt[i] = 0; }  // self-loop weight 1
}

__global__ void deg_acc_kernel(const int* __restrict__ dst,
                               const float* __restrict__ ew, int E, int n) {
    int e = blockIdx.x * blockDim.x + threadIdx.x;
    if (e < E) {
        int d = dst[e];
        if ((unsigned)d < (unsigned)n) {
            atomicAdd(&g_deg[d], ew[e]);
            atomicAdd(&g_cnt[d], 1);
        }
    }
}

// ---------------- scan phase A + fused dinv ----------------
__global__ void scan_partial_kernel(int n) {
    __shared__ int sm[256];
    int t = threadIdx.x;
    int base = blockIdx.x * SCAN_ITEMS;
    int s = 0;
    #pragma unroll
    for (int i = 0; i < SCAN_ITEMS / 256; i++) {
        int idx = base + i * 256 + t;
        if (idx < n) {
            s += g_cnt[idx];
            float d = g_deg[idx];
            g_dinv[idx] = d > 0.f ? rsqrtf(d) : 0.f;
        }
    }
    sm[t] = s;
    __syncthreads();
    #pragma unroll
    for (int off = 128; off > 0; off >>= 1) {
        if (t < off) sm[t] += sm[t + off];
        __syncthreads();
    }
    if (t == 0) g_bsum[blockIdx.x] = sm[0];
}

__global__ void scan_blocks_kernel(int nblk, int n) {
    __shared__ int sm[128];
    int t = threadIdx.x;
    sm[t] = (t < nblk) ? g_bsum[t] : 0;
    __syncthreads();
    for (int off = 1; off < 128; off <<= 1) {
        int v = (t >= off) ? sm[t - off] : 0;
        __syncthreads();
        sm[t] += v;
        __syncthreads();
    }
    if (t < nblk) g_boff[t] = (t == 0) ? 0 : sm[t - 1];
    if (t == nblk - 1) {
        g_boff[nblk] = sm[t];
        g_rowptr[n] = sm[t];
    }
}

__global__ void scan_final_kernel(int n) {
    constexpr int IPT = SCAN_ITEMS / 256;
    __shared__ int sm[256];
    int t = threadIdx.x;
    int base = blockIdx.x * SCAN_ITEMS + t * IPT;

    int v[IPT];
    int s = 0;
    #pragma unroll
    for (int i = 0; i < IPT; i++) {
        int idx = base + i;
        v[i] = (idx < n) ? g_cnt[idx] : 0;
        s += v[i];
    }
    sm[t] = s;
    __syncthreads();
    for (int off = 1; off < 256; off <<= 1) {
        int u = (t >= off) ? sm[t - off] : 0;
        __syncthreads();
        sm[t] += u;
        __syncthreads();
    }
    int run = g_boff[blockIdx.x] + ((t == 0) ? 0 : sm[t - 1]);
    #pragma unroll
    for (int i = 0; i < IPT; i++) {
        int idx = base + i;
        if (idx < n) {
            g_rowptr[idx] = run;
            g_cur[idx] = run;
            run += v[i];
        }
    }
}

// ---------------- scatter edges into CSR (col + precomputed norm) ----------------
__global__ void scatter_kernel(const int* __restrict__ src,
                               const int* __restrict__ dst,
                               const float* __restrict__ ew, int E, int n) {
    int e = blockIdx.x * blockDim.x + threadIdx.x;
    if (e >= E) return;
    int s = src[e];
    int d = dst[e];
    if ((unsigned)s >= (unsigned)n || (unsigned)d >= (unsigned)n) return;
    int pos = atomicAdd(&g_cur[d], 1);
    g_col[pos] = s;
    g_val[pos] = g_dinv[s] * ew[e] * g_dinv[d];
}

// ---------------- GEMM: g_h = X @ W  (K=128, BK=16, FFMA2, reg-prefetch pipeline) ----------------
template <int FOUT>
__global__ void gemm_kernel(const float* __restrict__ Xext,
                            const float* __restrict__ W,
                            int n, int useExt) {
    constexpr int K = KDIM, BK = 16, BM = 128, XS = BM + 4;
    constexpr int CG = FOUT / 4;          // 32 (F=128) or 16 (F=64)
    constexpr int NRG = 256 / CG;         // 8 or 16
    constexpr int RPT = BM / NRG;         // 16 or 8
    constexpr int NP = RPT / 2;           // row pairs per thread
    constexpr int NW = (BK * FOUT) / (4 * 256);   // W float4 per thread: 2 or 1
    constexpr int NX = (BM * BK) / (4 * 256);     // X float4 per thread: 2
    __shared__ float Ws[BK * FOUT];
    __shared__ float Xs[BK * XS];

    const float* X = useExt ? Xext : g_act;
    const int t = threadIdx.x;
    const int rowBase = blockIdx.x * BM;
    const int cg = t % CG, rg = t / CG;
    const int c0 = cg * 4, r0 = rg * RPT;

    unsigned long long acc2[NP][4];
    #pragma unroll
    for (int p = 0; p < NP; p++)
        #pragma unroll
        for (int c = 0; c < 4; c++) acc2[p][c] = 0ull;

    float4 wreg[NW], xreg[NX];

    // prologue: load chunk 0 into registers
    #pragma unroll
    for (int i = 0; i < NW; i++) {
        int idx = i * 256 + t;
        int kk = idx / (FOUT / 4), cc = idx % (FOUT / 4);
        wreg[i] = ((const float4*)(W + (size_t)kk * FOUT))[cc];
    }
    #pragma unroll
    for (int i = 0; i < NX; i++) {
        int idx = i * 256 + t;
        int row = idx >> 2, q = idx & 3;
        int grow = rowBase + row;
        xreg[i] = (grow < n) ? *(const float4*)(X + (size_t)grow * K + q * 4)
                             : make_float4(0.f, 0.f, 0.f, 0.f);
    }

    for (int kc = 0; kc < K; kc += BK) {
        // commit current registers to smem
        #pragma unroll
        for (int i = 0; i < NW; i++)
            ((float4*)Ws)[i * 256 + t] = wreg[i];
        #pragma unroll
        for (int i = 0; i < NX; i++) {
            int idx = i * 256 + t;
            int row = idx >> 2, q = idx & 3;
            Xs[(q * 4 + 0) * XS + row] = xreg[i].x;
            Xs[(q * 4 + 1) * XS + row] = xreg[i].y;
            Xs[(q * 4 + 2) * XS + row] = xreg[i].z;
            Xs[(q * 4 + 3) * XS + row] = xreg[i].w;
        }
        __syncthreads();

        // prefetch next chunk into registers (overlaps with compute below)
        int kn = kc + BK;
        if (kn < K) {
            #pragma unroll
            for (int i = 0; i < NW; i++) {
                int idx = i * 256 + t;
                int kk = idx / (FOUT / 4), cc = idx % (FOUT / 4);
                wreg[i] = ((const float4*)(W + (size_t)(kn + kk) * FOUT))[cc];
            }
            #pragma unroll
            for (int i = 0; i < NX; i++) {
                int idx = i * 256 + t;
                int row = idx >> 2, q = idx & 3;
                int grow = rowBase + row;
                xreg[i] = (grow < n) ? *(const float4*)(X + (size_t)grow * K + kn + q * 4)
                                     : make_float4(0.f, 0.f, 0.f, 0.f);
            }
        }

        #pragma unroll
        for (int k = 0; k < BK; k++) {
            float4 wv = *(const float4*)&Ws[k * FOUT + c0];
            unsigned long long wp0 = pk2(wv.x), wp1 = pk2(wv.y),
                               wp2 = pk2(wv.z), wp3 = pk2(wv.w);
            #pragma unroll
            for (int pq = 0; pq < NP / 2; pq++) {
                ulonglong2 xp = *(const ulonglong2*)&Xs[k * XS + r0 + pq * 4];
                fma2(acc2[pq * 2 + 0][0], xp.x, wp0);
                fma2(acc2[pq * 2 + 0][1], xp.x, wp1);
                fma2(acc2[pq * 2 + 0][2], xp.x, wp2);
                fma2(acc2[pq * 2 + 0][3], xp.x, wp3);
                fma2(acc2[pq * 2 + 1][0], xp.y, wp0);
                fma2(acc2[pq * 2 + 1][1], xp.y, wp1);
                fma2(acc2[pq * 2 + 1][2], xp.y, wp2);
                fma2(acc2[pq * 2 + 1][3], xp.y, wp3);
            }
        }
        __syncthreads();
    }

    #pragma unroll
    for (int p = 0; p < NP; p++) {
        float2 u0 = upk(acc2[p][0]), u1 = upk(acc2[p][1]),
               u2 = upk(acc2[p][2]), u3 = upk(acc2[p][3]);
        int rowA = rowBase + r0 + 2 * p;
        int rowB = rowA + 1;
        if (rowA < n)
            *(float4*)(g_h + (size_t)rowA * FOUT + c0) =
                make_float4(u0.x, u1.x, u2.x, u3.x);
        if (rowB < n)
            *(float4*)(g_h + (size_t)rowB * FOUT + c0) =
                make_float4(u0.y, u1.y, u2.y, u3.y);
    }
}

// ------- fused aggregate + bias + relu (F=128), warp per node -------
__global__ void agg_relu_kernel(const float* __restrict__ b, int n) {
    int w = (blockIdx.x * blockDim.x + threadIdx.x) >> 5;
    int lane = threadIdx.x & 31;
    if (w >= n) return;

    float di = g_dinv[w];
    float sv = di * di;
    float4 hs = *(const float4*)(g_h + (size_t)w * 128 + lane * 4);
    float4 acc = make_float4(hs.x * sv, hs.y * sv, hs.z * sv, hs.w * sv);

    int j = g_rowptr[w], end = g_rowptr[w + 1];
    for (; j + 4 <= end; j += 4) {
        int c0 = g_col[j], c1 = g_col[j + 1], c2 = g_col[j + 2], c3 = g_col[j + 3];
        float v0 = g_val[j], v1 = g_val[j + 1], v2 = g_val[j + 2], v3 = g_val[j + 3];
        float4 x0 = *(const float4*)(g_h + (size_t)c0 * 128 + lane * 4);
        float4 x1 = *(const float4*)(g_h + (size_t)c1 * 128 + lane * 4);
        float4 x2 = *(const float4*)(g_h + (size_t)c2 * 128 + lane * 4);
        float4 x3 = *(const float4*)(g_h + (size_t)c3 * 128 + lane * 4);
        acc.x += v0 * x0.x + v1 * x1.x + v2 * x2.x + v3 * x3.x;
        acc.y += v0 * x0.y + v1 * x1.y + v2 * x2.y + v3 * x3.y;
        acc.z += v0 * x0.z + v1 * x1.z + v2 * x2.z + v3 * x3.z;
        acc.w += v0 * x0.w + v1 * x1.w + v2 * x2.w + v3 * x3.w;
    }
    for (; j < end; j++) {
        int c0 = g_col[j];
        float v0 = g_val[j];
        float4 x0 = *(const float4*)(g_h + (size_t)c0 * 128 + lane * 4);
        acc.x += v0 * x0.x; acc.y += v0 * x0.y;
        acc.z += v0 * x0.z; acc.w += v0 * x0.w;
    }

    float4 bb = *(const float4*)(b + lane * 4);
    acc.x = fmaxf(acc.x + bb.x, 0.f);
    acc.y = fmaxf(acc.y + bb.y, 0.f);
    acc.z = fmaxf(acc.z + bb.z, 0.f);
    acc.w = fmaxf(acc.w + bb.w, 0.f);
    *(float4*)(g_act + (size_t)w * 128 + lane * 4) = acc;
}

// ------- fused aggregate + bias + log_softmax (F=64), warp per node -------
__global__ void agg_lsm_kernel(const float* __restrict__ b,
                               float* __restrict__ out, int n) {
    int w = (blockIdx.x * blockDim.x + threadIdx.x) >> 5;
    int lane = threadIdx.x & 31;
    if (w >= n) return;

    float di = g_dinv[w];
    float sv = di * di;
    float2 hs = *(const float2*)(g_h + (size_t)w * 64 + lane * 2);
    float2 acc = make_float2(hs.x * sv, hs.y * sv);

    int j = g_rowptr[w], end = g_rowptr[w + 1];
    for (; j + 4 <= end; j += 4) {
        int c0 = g_col[j], c1 = g_col[j + 1], c2 = g_col[j + 2], c3 = g_col[j + 3];
        float v0 = g_val[j], v1 = g_val[j + 1], v2 = g_val[j + 2], v3 = g_val[j + 3];
        float2 x0 = *(const float2*)(g_h + (size_t)c0 * 64 + lane * 2);
        float2 x1 = *(const float2*)(g_h + (size_t)c1 * 64 + lane * 2);
        float2 x2 = *(const float2*)(g_h + (size_t)c2 * 64 + lane * 2);
        float2 x3 = *(const float2*)(g_h + (size_t)c3 * 64 + lane * 2);
        acc.x += v0 * x0.x + v1 * x1.x + v2 * x2.x + v3 * x3.x;
        acc.y += v0 * x0.y + v1 * x1.y + v2 * x2.y + v3 * x3.y;
    }
    for (; j < end; j++) {
        int c0 = g_col[j];
        float v0 = g_val[j];
        float2 x0 = *(const float2*)(g_h + (size_t)c0 * 64 + lane * 2);
        acc.x += v0 * x0.x; acc.y += v0 * x0.y;
    }

    float v0 = acc.x + b[lane * 2];
    float v1 = acc.y + b[lane * 2 + 1];

    float m = fmaxf(v0, v1);
    #pragma unroll
    for (int o = 16; o > 0; o >>= 1)
        m = fmaxf(m, __shfl_xor_sync(0xffffffffu, m, o));
    float s = expf(v0 - m) + expf(v1 - m);
    #pragma unroll
    for (int o = 16; o > 0; o >>= 1)
        s += __shfl_xor_sync(0xffffffffu, s, o);
    float lse = m + logf(s);

    *(float2*)(out + (size_t)w * 64 + lane * 2) = make_float2(v0 - lse, v1 - lse);
}

// ---------------- launch ----------------
static inline int cdiv(int a, int b) { return (a + b - 1) / b; }

extern "C" void kernel_launch(void* const* d_in, const int* in_sizes, int n_in,
                              void* d_out, int out_size) {
    const float* x = (const float*)d_in[0];
    const int* ei = (const int*)d_in[1];      // int32 edge_index [2, E]
    const float* ew = (const float*)d_in[2];
    const float* W1 = (const float*)d_in[3];
    const float* b1 = (const float*)d_in[4];
    const float* W2 = (const float*)d_in[5];
    const float* b2 = (const float*)d_in[6];
    const float* W3 = (const float*)d_in[7];
    const float* b3 = (const float*)d_in[8];
    float* outp = (float*)d_out;

    const int n = in_sizes[0] / 128;
    const int E = in_sizes[2];
    const int* srcI = ei;
    const int* dstI = ei + E;
    const int nblk = cdiv(n, SCAN_ITEMS);

    // ---- gcn_norm + CSR build (sequential) ----
    deg_init_kernel<<<cdiv(n, 256), 256>>>(n);
    deg_acc_kernel<<<cdiv(E, 256), 256>>>(dstI, ew, E, n);
    scan_partial_kernel<<<nblk, 256>>>(n);   // also computes dinv
    scan_blocks_kernel<<<1, 128>>>(nblk, n);
    scan_final_kernel<<<nblk, 256>>>(n);
    scatter_kernel<<<cdiv(E, 256), 256>>>(srcI, dstI, ew, E, n);

    // ---- layer 1: 128 -> 128, relu ----
    gemm_kernel<128><<<cdiv(n, 128), 256>>>(x, W1, n, 1);
    agg_relu_kernel<<<cdiv(n * 32, 256), 256>>>(b1, n);

    // ---- layer 2: 128 -> 128, relu ----
    gemm_kernel<128><<<cdiv(n, 128), 256>>>(x, W2, n, 0);
    agg_relu_kernel<<<cdiv(n * 32, 256), 256>>>(b2, n);

    // ---- layer 3: 128 -> 64, log_softmax ----
    gemm_kernel<64><<<cdiv(n, 128), 256>>>(x, W3, n, 0);
    agg_lsm_kernel<<<cdiv(n * 32, 256), 256>>>(b3, outp, n);
}

// round 11
// speedup vs baseline: 1.0251x; 1.0251x over previous
#include <cuda_runtime.h>
#include <cstdint>

#define NMAX 100000
#define EMAX 1600000
#define KDIM 128
#define SCAN_ITEMS 1024
#define SCAN_NBLK ((NMAX + SCAN_ITEMS - 1) / SCAN_ITEMS)

// -------- scratch (no allocations allowed; referenced directly from kernels) --------
__device__ __align__(16) float g_deg[NMAX];
__device__ __align__(16) float g_dinv[NMAX];
__device__ __align__(16) int   g_cnt[NMAX];
__device__ __align__(16) int   g_cur[NMAX];
__device__ __align__(16) int   g_rowptr[NMAX + 1];
__device__ __align__(16) int   g_bsum[SCAN_NBLK];
__device__ __align__(16) int   g_boff[SCAN_NBLK + 1];
__device__ __align__(16) int2  g_edge[EMAX];   // packed (col, val-as-int)
__device__ __align__(16) float g_h[(size_t)NMAX * 128];
__device__ __align__(16) float g_act[(size_t)NMAX * 128];

// -------- packed f32x2 helpers (FFMA2 path, bit-exact fp32) --------
__device__ __forceinline__ unsigned long long pk2(float a) {
    unsigned long long r;
    asm("mov.b64 %0, {%1, %1};" : "=l"(r) : "f"(a));
    return r;
}
__device__ __forceinline__ void fma2(unsigned long long& d,
                                     unsigned long long a,
                                     unsigned long long b) {
    asm("fma.rn.f32x2 %0, %1, %2, %0;" : "+l"(d) : "l"(a), "l"(b));
}
__device__ __forceinline__ float2 upk(unsigned long long v) {
    float2 r;
    asm("mov.b64 {%0, %1}, %2;" : "=f"(r.x), "=f"(r.y) : "l"(v));
    return r;
}

// ---------------- degree / histogram init ----------------
__global__ void deg_init_kernel(int n) {
    int i = blockIdx.x * blockDim.x + threadIdx.x;
    if (i < n) { g_deg[i] = 1.0f; g_cnt[i] = 0; }  // self-loop weight 1
}

__global__ void deg_acc_kernel(const int* __restrict__ dst,
                               const float* __restrict__ ew, int E, int n) {
    int e = blockIdx.x * blockDim.x + threadIdx.x;
    if (e < E) {
        int d = dst[e];
        if ((unsigned)d < (unsigned)n) {
            atomicAdd(&g_deg[d], ew[e]);
            atomicAdd(&g_cnt[d], 1);
        }
    }
}

__global__ void dinv_kernel(int n) {
    int i = blockIdx.x * blockDim.x + threadIdx.x;
    if (i < n) {
        float d = g_deg[i];
        g_dinv[i] = d > 0.f ? rsqrtf(d) : 0.f;
    }
}

// ---------------- 3-phase grid-wide exclusive scan: cnt -> rowptr, cur ----------------
__global__ void scan_partial_kernel(int n) {
    __shared__ int sm[256];
    int t = threadIdx.x;
    int base = blockIdx.x * SCAN_ITEMS;
    int s = 0;
    #pragma unroll
    for (int i = 0; i < SCAN_ITEMS / 256; i++) {
        int idx = base + i * 256 + t;
        if (idx < n) s += g_cnt[idx];
    }
    sm[t] = s;
    __syncthreads();
    #pragma unroll
    for (int off = 128; off > 0; off >>= 1) {
        if (t < off) sm[t] += sm[t + off];
        __syncthreads();
    }
    if (t == 0) g_bsum[blockIdx.x] = sm[0];
}

__global__ void scan_blocks_kernel(int nblk, int n) {
    __shared__ int sm[128];
    int t = threadIdx.x;
    sm[t] = (t < nblk) ? g_bsum[t] : 0;
    __syncthreads();
    for (int off = 1; off < 128; off <<= 1) {
        int v = (t >= off) ? sm[t - off] : 0;
        __syncthreads();
        sm[t] += v;
        __syncthreads();
    }
    if (t < nblk) g_boff[t] = (t == 0) ? 0 : sm[t - 1];
    if (t == nblk - 1) {
        g_boff[nblk] = sm[t];
        g_rowptr[n] = sm[t];
    }
}

__global__ void scan_final_kernel(int n) {
    constexpr int IPT = SCAN_ITEMS / 256;
    __shared__ int sm[256];
    int t = threadIdx.x;
    int base = blockIdx.x * SCAN_ITEMS + t * IPT;

    int v[IPT];
    int s = 0;
    #pragma unroll
    for (int i = 0; i < IPT; i++) {
        int idx = base + i;
        v[i] = (idx < n) ? g_cnt[idx] : 0;
        s += v[i];
    }
    sm[t] = s;
    __syncthreads();
    for (int off = 1; off < 256; off <<= 1) {
        int u = (t >= off) ? sm[t - off] : 0;
        __syncthreads();
        sm[t] += u;
        __syncthreads();
    }
    int run = g_boff[blockIdx.x] + ((t == 0) ? 0 : sm[t - 1]);
    #pragma unroll
    for (int i = 0; i < IPT; i++) {
        int idx = base + i;
        if (idx < n) {
            g_rowptr[idx] = run;
            g_cur[idx] = run;
            run += v[i];
        }
    }
}

// ---------------- scatter edges into CSR (packed col+norm) ----------------
__global__ void scatter_kernel(const int* __restrict__ src,
                               const int* __restrict__ dst,
                               const float* __restrict__ ew, int E, int n) {
    int e = blockIdx.x * blockDim.x + threadIdx.x;
    if (e >= E) return;
    int s = src[e];
    int d = dst[e];
    if ((unsigned)s >= (unsigned)n || (unsigned)d >= (unsigned)n) return;
    int pos = atomicAdd(&g_cur[d], 1);
    float norm = g_dinv[s] * ew[e] * g_dinv[d];
    g_edge[pos] = make_int2(s, __float_as_int(norm));
}

// ---------------- GEMM: g_h = X @ W  (K=128, BK=16, FFMA2 packed row-pairs) ----------------
// R7-proven config: 256 threads, BM=128, BK=16, simple load loops, no prefetch.
template <int FOUT>
__global__ void gemm_kernel(const float* __restrict__ Xext,
                            const float* __restrict__ W,
                            int n, int useExt) {
    constexpr int K = KDIM, BK = 16, BM = 128, XS = BM + 4;
    constexpr int CG = FOUT / 4;          // 32 (F=128) or 16 (F=64)
    constexpr int NRG = 256 / CG;         // 8 or 16
    constexpr int RPT = BM / NRG;         // 16 or 8
    constexpr int NP = RPT / 2;           // row pairs per thread
    __shared__ float Ws[BK * FOUT];
    __shared__ float Xs[BK * XS];

    const float* X = useExt ? Xext : g_act;
    const int t = threadIdx.x;
    const int rowBase = blockIdx.x * BM;
    const int cg = t % CG, rg = t / CG;
    const int c0 = cg * 4, r0 = rg * RPT;

    unsigned long long acc2[NP][4];
    #pragma unroll
    for (int p = 0; p < NP; p++)
        #pragma unroll
        for (int c = 0; c < 4; c++) acc2[p][c] = 0ull;

    for (int kc = 0; kc < K; kc += BK) {
        // W chunk: BK*FOUT floats, coalesced float4
        #pragma unroll
        for (int i = t; i < BK * FOUT / 4; i += 256) {
            int kk = i / (FOUT / 4), cc = i % (FOUT / 4);
            ((float4*)Ws)[i] =
                ((const float4*)(W + (size_t)(kc + kk) * FOUT))[cc];
        }
        // X chunk transposed: BM*BK/4 = 512 float4, 2 per thread
        #pragma unroll
        for (int p = 0; p < 2; p++) {
            int idx = p * 256 + t;          // 0..511
            int row = idx >> 2;             // 0..127
            int q = idx & 3;                // float4 within BK=16
            int grow = rowBase + row;
            float4 v = make_float4(0.f, 0.f, 0.f, 0.f);
            if (grow < n) v = *(const float4*)(X + (size_t)grow * K + kc + q * 4);
            Xs[(q * 4 + 0) * XS + row] = v.x;
            Xs[(q * 4 + 1) * XS + row] = v.y;
            Xs[(q * 4 + 2) * XS + row] = v.z;
            Xs[(q * 4 + 3) * XS + row] = v.w;
        }
        __syncthreads();

        #pragma unroll
        for (int k = 0; k < BK; k++) {
            float4 wv = *(const float4*)&Ws[k * FOUT + c0];
            unsigned long long wp0 = pk2(wv.x), wp1 = pk2(wv.y),
                               wp2 = pk2(wv.z), wp3 = pk2(wv.w);
            #pragma unroll
            for (int pq = 0; pq < NP / 2; pq++) {
                ulonglong2 xp = *(const ulonglong2*)&Xs[k * XS + r0 + pq * 4];
                fma2(acc2[pq * 2 + 0][0], xp.x, wp0);
                fma2(acc2[pq * 2 + 0][1], xp.x, wp1);
                fma2(acc2[pq * 2 + 0][2], xp.x, wp2);
                fma2(acc2[pq * 2 + 0][3], xp.x, wp3);
                fma2(acc2[pq * 2 + 1][0], xp.y, wp0);
                fma2(acc2[pq * 2 + 1][1], xp.y, wp1);
                fma2(acc2[pq * 2 + 1][2], xp.y, wp2);
                fma2(acc2[pq * 2 + 1][3], xp.y, wp3);
            }
        }
        __syncthreads();
    }

    #pragma unroll
    for (int p = 0; p < NP; p++) {
        float2 u0 = upk(acc2[p][0]), u1 = upk(acc2[p][1]),
               u2 = upk(acc2[p][2]), u3 = upk(acc2[p][3]);
        int rowA = rowBase + r0 + 2 * p;
        int rowB = rowA + 1;
        if (rowA < n)
            *(float4*)(g_h + (size_t)rowA * FOUT + c0) =
                make_float4(u0.x, u1.x, u2.x, u3.x);
        if (rowB < n)
            *(float4*)(g_h + (size_t)rowB * FOUT + c0) =
                make_float4(u0.y, u1.y, u2.y, u3.y);
    }
}

// ------- fused aggregate + bias + relu (F=128), warp per node -------
__global__ void agg_relu_kernel(const float* __restrict__ b, int n) {
    int w = (blockIdx.x * blockDim.x + threadIdx.x) >> 5;
    int lane = threadIdx.x & 31;
    if (w >= n) return;

    float di = g_dinv[w];
    float sv = di * di;
    float4 hs = *(const float4*)(g_h + (size_t)w * 128 + lane * 4);
    float4 acc = make_float4(hs.x * sv, hs.y * sv, hs.z * sv, hs.w * sv);

    int j = g_rowptr[w], end = g_rowptr[w + 1];
    for (; j + 4 <= end; j += 4) {
        int2 p0 = g_edge[j],     p1 = g_edge[j + 1];
        int2 p2 = g_edge[j + 2], p3 = g_edge[j + 3];
        float v0 = __int_as_float(p0.y), v1 = __int_as_float(p1.y);
        float v2 = __int_as_float(p2.y), v3 = __int_as_float(p3.y);
        float4 x0 = *(const float4*)(g_h + (size_t)p0.x * 128 + lane * 4);
        float4 x1 = *(const float4*)(g_h + (size_t)p1.x * 128 + lane * 4);
        float4 x2 = *(const float4*)(g_h + (size_t)p2.x * 128 + lane * 4);
        float4 x3 = *(const float4*)(g_h + (size_t)p3.x * 128 + lane * 4);
        acc.x += v0 * x0.x + v1 * x1.x + v2 * x2.x + v3 * x3.x;
        acc.y += v0 * x0.y + v1 * x1.y + v2 * x2.y + v3 * x3.y;
        acc.z += v0 * x0.z + v1 * x1.z + v2 * x2.z + v3 * x3.z;
        acc.w += v0 * x0.w + v1 * x1.w + v2 * x2.w + v3 * x3.w;
    }
    for (; j < end; j++) {
        int2 p0 = g_edge[j];
        float v0 = __int_as_float(p0.y);
        float4 x0 = *(const float4*)(g_h + (size_t)p0.x * 128 + lane * 4);
        acc.x += v0 * x0.x; acc.y += v0 * x0.y;
        acc.z += v0 * x0.z; acc.w += v0 * x0.w;
    }

    float4 bb = *(const float4*)(b + lane * 4);
    acc.x = fmaxf(acc.x + bb.x, 0.f);
    acc.y = fmaxf(acc.y + bb.y, 0.f);
    acc.z = fmaxf(acc.z + bb.z, 0.f);
    acc.w = fmaxf(acc.w + bb.w, 0.f);
    *(float4*)(g_act + (size_t)w * 128 + lane * 4) = acc;
}

// ------- fused aggregate + bias + log_softmax (F=64), warp per node -------
__global__ void agg_lsm_kernel(const float* __restrict__ b,
                               float* __restrict__ out, int n) {
    int w = (blockIdx.x * blockDim.x + threadIdx.x) >> 5;
    int lane = threadIdx.x & 31;
    if (w >= n) return;

    float di = g_dinv[w];
    float sv = di * di;
    float2 hs = *(const float2*)(g_h + (size_t)w * 64 + lane * 2);
    float2 acc = make_float2(hs.x * sv, hs.y * sv);

    int j = g_rowptr[w], end = g_rowptr[w + 1];
    for (; j + 4 <= end; j += 4) {
        int2 p0 = g_edge[j],     p1 = g_edge[j + 1];
        int2 p2 = g_edge[j + 2], p3 = g_edge[j + 3];
        float v0 = __int_as_float(p0.y), v1 = __int_as_float(p1.y);
        float v2 = __int_as_float(p2.y), v3 = __int_as_float(p3.y);
        float2 x0 = *(const float2*)(g_h + (size_t)p0.x * 64 + lane * 2);
        float2 x1 = *(const float2*)(g_h + (size_t)p1.x * 64 + lane * 2);
        float2 x2 = *(const float2*)(g_h + (size_t)p2.x * 64 + lane * 2);
        float2 x3 = *(const float2*)(g_h + (size_t)p3.x * 64 + lane * 2);
        acc.x += v0 * x0.x + v1 * x1.x + v2 * x2.x + v3 * x3.x;
        acc.y += v0 * x0.y + v1 * x1.y + v2 * x2.y + v3 * x3.y;
    }
    for (; j < end; j++) {
        int2 p0 = g_edge[j];
        float v0 = __int_as_float(p0.y);
        float2 x0 = *(const float2*)(g_h + (size_t)p0.x * 64 + lane * 2);
        acc.x += v0 * x0.x; acc.y += v0 * x0.y;
    }

    float v0 = acc.x + b[lane * 2];
    float v1 = acc.y + b[lane * 2 + 1];

    float m = fmaxf(v0, v1);
    #pragma unroll
    for (int o = 16; o > 0; o >>= 1)
        m = fmaxf(m, __shfl_xor_sync(0xffffffffu, m, o));
    float s = expf(v0 - m) + expf(v1 - m);
    #pragma unroll
    for (int o = 16; o > 0; o >>= 1)
        s += __shfl_xor_sync(0xffffffffu, s, o);
    float lse = m + logf(s);

    *(float2*)(out + (size_t)w * 64 + lane * 2) = make_float2(v0 - lse, v1 - lse);
}

// ---------------- launch ----------------
static inline int cdiv(int a, int b) { return (a + b - 1) / b; }

extern "C" void kernel_launch(void* const* d_in, const int* in_sizes, int n_in,
                              void* d_out, int out_size) {
    const float* x = (const float*)d_in[0];
    const int* ei = (const int*)d_in[1];      // int32 edge_index [2, E]
    const float* ew = (const float*)d_in[2];
    const float* W1 = (const float*)d_in[3];
    const float* b1 = (const float*)d_in[4];
    const float* W2 = (const float*)d_in[5];
    const float* b2 = (const float*)d_in[6];
    const float* W3 = (const float*)d_in[7];
    const float* b3 = (const float*)d_in[8];
    float* outp = (float*)d_out;

    const int n = in_sizes[0] / 128;
    const int E = in_sizes[2];
    const int* srcI = ei;
    const int* dstI = ei + E;
    const int nblk = cdiv(n, SCAN_ITEMS);

    // ---- gcn_norm + CSR build (sequential) ----
    deg_init_kernel<<<cdiv(n, 256), 256>>>(n);
    deg_acc_kernel<<<cdiv(E, 256), 256>>>(dstI, ew, E, n);
    dinv_kernel<<<cdiv(n, 256), 256>>>(n);
    scan_partial_kernel<<<nblk, 256>>>(n);
    scan_blocks_kernel<<<1, 128>>>(nblk, n);
    scan_final_kernel<<<nblk, 256>>>(n);
    scatter_kernel<<<cdiv(E, 256), 256>>>(srcI, dstI, ew, E, n);

    // ---- layer 1: 128 -> 128, relu ----
    gemm_kernel<128><<<cdiv(n, 128), 256>>>(x, W1, n, 1);
    agg_relu_kernel<<<cdiv(n * 32, 256), 256>>>(b1, n);

    // ---- layer 2: 128 -> 128, relu ----
    gemm_kernel<128><<<cdiv(n, 128), 256>>>(x, W2, n, 0);
    agg_relu_kernel<<<cdiv(n * 32, 256), 256>>>(b2, n);

    // ---- layer 3: 128 -> 64, log_softmax ----
    gemm_kernel<64><<<cdiv(n, 128), 256>>>(x, W3, n, 0);
    agg_lsm_kernel<<<cdiv(n * 32, 256), 256>>>(b3, outp, n);
}

// round 13
// speedup vs baseline: 1.1178x; 1.0905x over previous
#include <cuda_runtime.h>
#include <cuda_fp16.h>
#include <cstdint>

#define NMAX 100000
#define EMAX 1600000
#define KDIM 128
#define SCAN_ITEMS 1024
#define SCAN_NBLK ((NMAX + SCAN_ITEMS - 1) / SCAN_ITEMS)

// -------- scratch (no allocations allowed; referenced directly from kernels) --------
__device__ __align__(16) float  g_deg[NMAX];
__device__ __align__(16) float  g_dinv[NMAX];
__device__ __align__(16) int    g_cnt[NMAX];
__device__ __align__(16) int    g_cur[NMAX];
__device__ __align__(16) int    g_rowptr[NMAX + 1];
__device__ __align__(16) int    g_bsum[SCAN_NBLK];
__device__ __align__(16) int    g_boff[SCAN_NBLK + 1];
__device__ __align__(16) int    g_col[EMAX];
__device__ __align__(16) float  g_val[EMAX];
__device__ __align__(16) float  g_h[(size_t)NMAX * 128];
__device__ __align__(16) __half g_hh[(size_t)NMAX * 128];   // fp16 copy for gathers
__device__ __align__(16) float  g_act[(size_t)NMAX * 128];

// -------- packed f32x2 helpers (FFMA2 path, bit-exact fp32) --------
__device__ __forceinline__ unsigned long long pk2(float a) {
    unsigned long long r;
    asm("mov.b64 %0, {%1, %1};" : "=l"(r) : "f"(a));
    return r;
}
__device__ __forceinline__ void fma2(unsigned long long& d,
                                     unsigned long long a,
                                     unsigned long long b) {
    asm("fma.rn.f32x2 %0, %1, %2, %0;" : "+l"(d) : "l"(a), "l"(b));
}
__device__ __forceinline__ float2 upk(unsigned long long v) {
    float2 r;
    asm("mov.b64 {%0, %1}, %2;" : "=f"(r.x), "=f"(r.y) : "l"(v));
    return r;
}

// half2 pair for 8-byte vector load/store
struct __align__(8) half2x2 { __half2 a, b; };

// ---------------- degree / histogram init ----------------
__global__ void deg_init_kernel(int n) {
    int i = blockIdx.x * blockDim.x + threadIdx.x;
    if (i < n) { g_deg[i] = 1.0f; g_cnt[i] = 0; }  // self-loop weight 1
}

__global__ void deg_acc_kernel(const int* __restrict__ dst,
                               const float* __restrict__ ew, int E, int n) {
    int e = blockIdx.x * blockDim.x + threadIdx.x;
    if (e < E) {
        int d = dst[e];
        if ((unsigned)d < (unsigned)n) {
            atomicAdd(&g_deg[d], ew[e]);
            atomicAdd(&g_cnt[d], 1);
        }
    }
}

__global__ void dinv_kernel(int n) {
    int i = blockIdx.x * blockDim.x + threadIdx.x;
    if (i < n) {
        float d = g_deg[i];
        g_dinv[i] = d > 0.f ? rsqrtf(d) : 0.f;
    }
}

// ---------------- 3-phase grid-wide exclusive scan: cnt -> rowptr, cur ----------------
__global__ void scan_partial_kernel(int n) {
    __shared__ int sm[256];
    int t = threadIdx.x;
    int base = blockIdx.x * SCAN_ITEMS;
    int s = 0;
    #pragma unroll
    for (int i = 0; i < SCAN_ITEMS / 256; i++) {
        int idx = base + i * 256 + t;
        if (idx < n) s += g_cnt[idx];
    }
    sm[t] = s;
    __syncthreads();
    #pragma unroll
    for (int off = 128; off > 0; off >>= 1) {
        if (t < off) sm[t] += sm[t + off];
        __syncthreads();
    }
    if (t == 0) g_bsum[blockIdx.x] = sm[0];
}

__global__ void scan_blocks_kernel(int nblk, int n) {
    __shared__ int sm[128];
    int t = threadIdx.x;
    sm[t] = (t < nblk) ? g_bsum[t] : 0;
    __syncthreads();
    for (int off = 1; off < 128; off <<= 1) {
        int v = (t >= off) ? sm[t - off] : 0;
        __syncthreads();
        sm[t] += v;
        __syncthreads();
    }
    if (t < nblk) g_boff[t] = (t == 0) ? 0 : sm[t - 1];
    if (t == nblk - 1) {
        g_boff[nblk] = sm[t];
        g_rowptr[n] = sm[t];
    }
}

__global__ void scan_final_kernel(int n) {
    constexpr int IPT = SCAN_ITEMS / 256;
    __shared__ int sm[256];
    int t = threadIdx.x;
    int base = blockIdx.x * SCAN_ITEMS + t * IPT;

    int v[IPT];
    int s = 0;
    #pragma unroll
    for (int i = 0; i < IPT; i++) {
        int idx = base + i;
        v[i] = (idx < n) ? g_cnt[idx] : 0;
        s += v[i];
    }
    sm[t] = s;
    __syncthreads();
    for (int off = 1; off < 256; off <<= 1) {
        int u = (t >= off) ? sm[t - off] : 0;
        __syncthreads();
        sm[t] += u;
        __syncthreads();
    }
    int run = g_boff[blockIdx.x] + ((t == 0) ? 0 : sm[t - 1]);
    #pragma unroll
    for (int i = 0; i < IPT; i++) {
        int idx = base + i;
        if (idx < n) {
            g_rowptr[idx] = run;
            g_cur[idx] = run;
            run += v[i];
        }
    }
}

// ---------------- scatter edges into CSR (col + precomputed norm) ----------------
__global__ void scatter_kernel(const int* __restrict__ src,
                               const int* __restrict__ dst,
                               const float* __restrict__ ew, int E, int n) {
    int e = blockIdx.x * blockDim.x + threadIdx.x;
    if (e >= E) return;
    int s = src[e];
    int d = dst[e];
    if ((unsigned)s >= (unsigned)n || (unsigned)d >= (unsigned)n) return;
    int pos = atomicAdd(&g_cur[d], 1);
    g_col[pos] = s;
    g_val[pos] = g_dinv[s] * ew[e] * g_dinv[d];
}

// ---------------- GEMM: g_h(+g_hh fp16) = X @ W  (K=128, BK=16, FFMA2) ----------------
template <int FOUT>
__global__ void gemm_kernel(const float* __restrict__ Xext,
                            const float* __restrict__ W,
                            int n, int useExt) {
    constexpr int K = KDIM, BK = 16, BM = 128, XS = BM + 4;
    constexpr int CG = FOUT / 4;          // 32 (F=128) or 16 (F=64)
    constexpr int NRG = 256 / CG;         // 8 or 16
    constexpr int RPT = BM / NRG;         // 16 or 8
    constexpr int NP = RPT / 2;           // row pairs per thread
    __shared__ float Ws[BK * FOUT];
    __shared__ float Xs[BK * XS];

    const float* X = useExt ? Xext : g_act;
    const int t = threadIdx.x;
    const int rowBase = blockIdx.x * BM;
    const int cg = t % CG, rg = t / CG;
    const int c0 = cg * 4, r0 = rg * RPT;

    unsigned long long acc2[NP][4];
    #pragma unroll
    for (int p = 0; p < NP; p++)
        #pragma unroll
        for (int c = 0; c < 4; c++) acc2[p][c] = 0ull;

    for (int kc = 0; kc < K; kc += BK) {
        #pragma unroll
        for (int i = t; i < BK * FOUT / 4; i += 256) {
            int kk = i / (FOUT / 4), cc = i % (FOUT / 4);
            ((float4*)Ws)[i] =
                ((const float4*)(W + (size_t)(kc + kk) * FOUT))[cc];
        }
        #pragma unroll
        for (int p = 0; p < 2; p++) {
            int idx = p * 256 + t;          // 0..511
            int row = idx >> 2;             // 0..127
            int q = idx & 3;                // float4 within BK=16
            int grow = rowBase + row;
            float4 v = make_float4(0.f, 0.f, 0.f, 0.f);
            if (grow < n) v = *(const float4*)(X + (size_t)grow * K + kc + q * 4);
            Xs[(q * 4 + 0) * XS + row] = v.x;
            Xs[(q * 4 + 1) * XS + row] = v.y;
            Xs[(q * 4 + 2) * XS + row] = v.z;
            Xs[(q * 4 + 3) * XS + row] = v.w;
        }
        __syncthreads();

        #pragma unroll
        for (int k = 0; k < BK; k++) {
            float4 wv = *(const float4*)&Ws[k * FOUT + c0];
            unsigned long long wp0 = pk2(wv.x), wp1 = pk2(wv.y),
                               wp2 = pk2(wv.z), wp3 = pk2(wv.w);
            #pragma unroll
            for (int pq = 0; pq < NP / 2; pq++) {
                ulonglong2 xp = *(const ulonglong2*)&Xs[k * XS + r0 + pq * 4];
                fma2(acc2[pq * 2 + 0][0], xp.x, wp0);
                fma2(acc2[pq * 2 + 0][1], xp.x, wp1);
                fma2(acc2[pq * 2 + 0][2], xp.x, wp2);
                fma2(acc2[pq * 2 + 0][3], xp.x, wp3);
                fma2(acc2[pq * 2 + 1][0], xp.y, wp0);
                fma2(acc2[pq * 2 + 1][1], xp.y, wp1);
                fma2(acc2[pq * 2 + 1][2], xp.y, wp2);
                fma2(acc2[pq * 2 + 1][3], xp.y, wp3);
            }
        }
        __syncthreads();
    }

    #pragma unroll
    for (int p = 0; p < NP; p++) {
        float2 u0 = upk(acc2[p][0]), u1 = upk(acc2[p][1]),
               u2 = upk(acc2[p][2]), u3 = upk(acc2[p][3]);
        int rowA = rowBase + r0 + 2 * p;
        int rowB = rowA + 1;
        if (rowA < n) {
            float4 fa = make_float4(u0.x, u1.x, u2.x, u3.x);
            *(float4*)(g_h + (size_t)rowA * FOUT + c0) = fa;
            half2x2 ha;
            ha.a = __floats2half2_rn(fa.x, fa.y);
            ha.b = __floats2half2_rn(fa.z, fa.w);
            *(half2x2*)(g_hh + (size_t)rowA * FOUT + c0) = ha;
        }
        if (rowB < n) {
            float4 fb = make_float4(u0.y, u1.y, u2.y, u3.y);
            *(float4*)(g_h + (size_t)rowB * FOUT + c0) = fb;
            half2x2 hb;
            hb.a = __floats2half2_rn(fb.x, fb.y);
            hb.b = __floats2half2_rn(fb.z, fb.w);
            *(half2x2*)(g_hh + (size_t)rowB * FOUT + c0) = hb;
        }
    }
}

// ------- fused aggregate + bias + relu (F=128), warp per node -------
// Self-loop term from exact fp32 g_h; neighbor gathers from fp16 g_hh (half bytes).
__global__ void agg_relu_kernel(const float* __restrict__ b, int n) {
    int w = (blockIdx.x * blockDim.x + threadIdx.x) >> 5;
    int lane = threadIdx.x & 31;
    if (w >= n) return;

    float di = g_dinv[w];
    float sv = di * di;
    float4 hs = *(const float4*)(g_h + (size_t)w * 128 + lane * 4);
    float4 acc = make_float4(hs.x * sv, hs.y * sv, hs.z * sv, hs.w * sv);

    int j = g_rowptr[w], end = g_rowptr[w + 1];
    for (; j + 4 <= end; j += 4) {
        int c0 = g_col[j], c1 = g_col[j + 1], c2 = g_col[j + 2], c3 = g_col[j + 3];
        float v0 = g_val[j], v1 = g_val[j + 1], v2 = g_val[j + 2], v3 = g_val[j + 3];
        half2x2 q0 = *(const half2x2*)(g_hh + (size_t)c0 * 128 + lane * 4);
        half2x2 q1 = *(const half2x2*)(g_hh + (size_t)c1 * 128 + lane * 4);
        half2x2 q2 = *(const half2x2*)(g_hh + (size_t)c2 * 128 + lane * 4);
        half2x2 q3 = *(const half2x2*)(g_hh + (size_t)c3 * 128 + lane * 4);
        float2 a0 = __half22float2(q0.a), b0 = __half22float2(q0.b);
        float2 a1 = __half22float2(q1.a), b1v = __half22float2(q1.b);
        float2 a2 = __half22float2(q2.a), b2v = __half22float2(q2.b);
        float2 a3 = __half22float2(q3.a), b3v = __half22float2(q3.b);
        acc.x += v0 * a0.x + v1 * a1.x + v2 * a2.x + v3 * a3.x;
        acc.y += v0 * a0.y + v1 * a1.y + v2 * a2.y + v3 * a3.y;
        acc.z += v0 * b0.x + v1 * b1v.x + v2 * b2v.x + v3 * b3v.x;
        acc.w += v0 * b0.y + v1 * b1v.y + v2 * b2v.y + v3 * b3v.y;
    }
    for (; j < end; j++) {
        int c0 = g_col[j];
        float v0 = g_val[j];
        half2x2 q0 = *(const half2x2*)(g_hh + (size_t)c0 * 128 + lane * 4);
        float2 a0 = __half22float2(q0.a), b0 = __half22float2(q0.b);
        acc.x += v0 * a0.x; acc.y += v0 * a0.y;
        acc.z += v0 * b0.x; acc.w += v0 * b0.y;
    }

    float4 bb = *(const float4*)(b + lane * 4);
    acc.x = fmaxf(acc.x + bb.x, 0.f);
    acc.y = fmaxf(acc.y + bb.y, 0.f);
    acc.z = fmaxf(acc.z + bb.z, 0.f);
    acc.w = fmaxf(acc.w + bb.w, 0.f);
    *(float4*)(g_act + (size_t)w * 128 + lane * 4) = acc;
}

// ------- fused aggregate + bias + log_softmax (F=64), warp per node -------
__global__ void agg_lsm_kernel(const float* __restrict__ b,
                               float* __restrict__ out, int n) {
    int w = (blockIdx.x * blockDim.x + threadIdx.x) >> 5;
    int lane = threadIdx.x & 31;
    if (w >= n) return;

    float di = g_dinv[w];
    float sv = di * di;
    float2 hs = *(const float2*)(g_h + (size_t)w * 64 + lane * 2);
    float2 acc = make_float2(hs.x * sv, hs.y * sv);

    int j = g_rowptr[w], end = g_rowptr[w + 1];
    for (; j + 4 <= end; j += 4) {
        int c0 = g_col[j], c1 = g_col[j + 1], c2 = g_col[j + 2], c3 = g_col[j + 3];
        float v0 = g_val[j], v1 = g_val[j + 1], v2 = g_val[j + 2], v3 = g_val[j + 3];
        __half2 u0 = *(const __half2*)(g_hh + (size_t)c0 * 64 + lane * 2);
        __half2 u1 = *(const __half2*)(g_hh + (size_t)c1 * 64 + lane * 2);
        __half2 u2 = *(const __half2*)(g_hh + (size_t)c2 * 64 + lane * 2);
        __half2 u3 = *(const __half2*)(g_hh + (size_t)c3 * 64 + lane * 2);
        float2 x0 = __half22float2(u0);
        float2 x1 = __half22float2(u1);
        float2 x2 = __half22float2(u2);
        float2 x3 = __half22float2(u3);
        acc.x += v0 * x0.x + v1 * x1.x + v2 * x2.x + v3 * x3.x;
        acc.y += v0 * x0.y + v1 * x1.y + v2 * x2.y + v3 * x3.y;
    }
    for (; j < end; j++) {
        int c0 = g_col[j];
        float v0 = g_val[j];
        __half2 u0 = *(const __half2*)(g_hh + (size_t)c0 * 64 + lane * 2);
        float2 x0 = __half22float2(u0);
        acc.x += v0 * x0.x; acc.y += v0 * x0.y;
    }

    float v0 = acc.x + b[lane * 2];
    float v1 = acc.y + b[lane * 2 + 1];

    float m = fmaxf(v0, v1);
    #pragma unroll
    for (int o = 16; o > 0; o >>= 1)
        m = fmaxf(m, __shfl_xor_sync(0xffffffffu, m, o));
    float s = expf(v0 - m) + expf(v1 - m);
    #pragma unroll
    for (int o = 16; o > 0; o >>= 1)
        s += __shfl_xor_sync(0xffffffffu, s, o);
    float lse = m + logf(s);

    *(float2*)(out + (size_t)w * 64 + lane * 2) = make_float2(v0 - lse, v1 - lse);
}

// ---------------- launch ----------------
static inline int cdiv(int a, int b) { return (a + b - 1) / b; }

extern "C" void kernel_launch(void* const* d_in, const int* in_sizes, int n_in,
                              void* d_out, int out_size) {
    const float* x = (const float*)d_in[0];
    const int* ei = (const int*)d_in[1];      // int32 edge_index [2, E]
    const float* ew = (const float*)d_in[2];
    const float* W1 = (const float*)d_in[3];
    const float* b1 = (const float*)d_in[4];
    const float* W2 = (const float*)d_in[5];
    const float* b2 = (const float*)d_in[6];
    const float* W3 = (const float*)d_in[7];
    const float* b3 = (const float*)d_in[8];
    float* outp = (float*)d_out;

    const int n = in_sizes[0] / 128;
    const int E = in_sizes[2];
    const int* srcI = ei;
    const int* dstI = ei + E;
    const int nblk = cdiv(n, SCAN_ITEMS);

    // ---- gcn_norm + CSR build (sequential) ----
    deg_init_kernel<<<cdiv(n, 256), 256>>>(n);
    deg_acc_kernel<<<cdiv(E, 256), 256>>>(dstI, ew, E, n);
    dinv_kernel<<<cdiv(n, 256), 256>>>(n);
    scan_partial_kernel<<<nblk, 256>>>(n);
    scan_blocks_kernel<<<1, 128>>>(nblk, n);
    scan_final_kernel<<<nblk, 256>>>(n);
    scatter_kernel<<<cdiv(E, 256), 256>>>(srcI, dstI, ew, E, n);

    // ---- layer 1: 128 -> 128, relu ----
    gemm_kernel<128><<<cdiv(n, 128), 256>>>(x, W1, n, 1);
    agg_relu_kernel<<<cdiv(n * 32, 256), 256>>>(b1, n);

    // ---- layer 2: 128 -> 128, relu ----
    gemm_kernel<128><<<cdiv(n, 128), 256>>>(x, W2, n, 0);
    agg_relu_kernel<<<cdiv(n * 32, 256), 256>>>(b2, n);

    // ---- layer 3: 128 -> 64, log_softmax ----
    gemm_kernel<64><<<cdiv(n, 128), 256>>>(x, W3, n, 0);
    agg_lsm_kernel<<<cdiv(n * 32, 256), 256>>>(b3, outp, n);
}

// round 14
// speedup vs baseline: 1.1852x; 1.0602x over previous
#include <cuda_runtime.h>
#include <cuda_fp16.h>
#include <cstdint>

#define NMAX 100000
#define EMAX 1600000
#define KDIM 128
#define SCAN_ITEMS 1024
#define SCAN_NBLK ((NMAX + SCAN_ITEMS - 1) / SCAN_ITEMS)

// -------- scratch (no allocations allowed; referenced directly from kernels) --------
__device__ __align__(16) float  g_deg[NMAX];
__device__ __align__(16) float  g_dinv[NMAX];
__device__ __align__(16) int    g_cnt[NMAX];
__device__ __align__(16) int    g_cur[NMAX];
__device__ __align__(16) int    g_rowptr[NMAX + 1];
__device__ __align__(16) int    g_bsum[SCAN_NBLK];
__device__ __align__(16) int    g_boff[SCAN_NBLK + 1];
__device__ __align__(16) int    g_col[EMAX];
__device__ __align__(16) float  g_val[EMAX];
__device__ __align__(16) __half g_hh[(size_t)NMAX * 128];   // fp16 hidden (GEMM out, agg in)
__device__ __align__(16) float  g_act[(size_t)NMAX * 128];

// -------- packed f32x2 helpers (FFMA2 path, bit-exact fp32) --------
__device__ __forceinline__ unsigned long long pk2(float a) {
    unsigned long long r;
    asm("mov.b64 %0, {%1, %1};" : "=l"(r) : "f"(a));
    return r;
}
__device__ __forceinline__ void fma2(unsigned long long& d,
                                     unsigned long long a,
                                     unsigned long long b) {
    asm("fma.rn.f32x2 %0, %1, %2, %0;" : "+l"(d) : "l"(a), "l"(b));
}
__device__ __forceinline__ float2 upk(unsigned long long v) {
    float2 r;
    asm("mov.b64 {%0, %1}, %2;" : "=f"(r.x), "=f"(r.y) : "l"(v));
    return r;
}

// half2 pair for 8-byte vector load/store
struct __align__(8) half2x2 { __half2 a, b; };

// ---------------- degree / histogram init ----------------
__global__ void deg_init_kernel(int n) {
    int i = blockIdx.x * blockDim.x + threadIdx.x;
    if (i < n) { g_deg[i] = 1.0f; g_cnt[i] = 0; }  // self-loop weight 1
}

__global__ void deg_acc_kernel(const int* __restrict__ dst,
                               const float* __restrict__ ew, int E, int n) {
    int e = blockIdx.x * blockDim.x + threadIdx.x;
    if (e < E) {
        int d = dst[e];
        if ((unsigned)d < (unsigned)n) {
            atomicAdd(&g_deg[d], ew[e]);
            atomicAdd(&g_cnt[d], 1);
        }
    }
}

__global__ void dinv_kernel(int n) {
    int i = blockIdx.x * blockDim.x + threadIdx.x;
    if (i < n) {
        float d = g_deg[i];
        g_dinv[i] = d > 0.f ? rsqrtf(d) : 0.f;
    }
}

// ---------------- 3-phase grid-wide exclusive scan: cnt -> rowptr, cur ----------------
__global__ void scan_partial_kernel(int n) {
    __shared__ int sm[256];
    int t = threadIdx.x;
    int base = blockIdx.x * SCAN_ITEMS;
    int s = 0;
    #pragma unroll
    for (int i = 0; i < SCAN_ITEMS / 256; i++) {
        int idx = base + i * 256 + t;
        if (idx < n) s += g_cnt[idx];
    }
    sm[t] = s;
    __syncthreads();
    #pragma unroll
    for (int off = 128; off > 0; off >>= 1) {
        if (t < off) sm[t] += sm[t + off];
        __syncthreads();
    }
    if (t == 0) g_bsum[blockIdx.x] = sm[0];
}

__global__ void scan_blocks_kernel(int nblk, int n) {
    __shared__ int sm[128];
    int t = threadIdx.x;
    sm[t] = (t < nblk) ? g_bsum[t] : 0;
    __syncthreads();
    for (int off = 1; off < 128; off <<= 1) {
        int v = (t >= off) ? sm[t - off] : 0;
        __syncthreads();
        sm[t] += v;
        __syncthreads();
    }
    if (t < nblk) g_boff[t] = (t == 0) ? 0 : sm[t - 1];
    if (t == nblk - 1) {
        g_boff[nblk] = sm[t];
        g_rowptr[n] = sm[t];
    }
}

__global__ void scan_final_kernel(int n) {
    constexpr int IPT = SCAN_ITEMS / 256;
    __shared__ int sm[256];
    int t = threadIdx.x;
    int base = blockIdx.x * SCAN_ITEMS + t * IPT;

    int v[IPT];
    int s = 0;
    #pragma unroll
    for (int i = 0; i < IPT; i++) {
        int idx = base + i;
        v[i] = (idx < n) ? g_cnt[idx] : 0;
        s += v[i];
    }
    sm[t] = s;
    __syncthreads();
    for (int off = 1; off < 256; off <<= 1) {
        int u = (t >= off) ? sm[t - off] : 0;
        __syncthreads();
        sm[t] += u;
        __syncthreads();
    }
    int run = g_boff[blockIdx.x] + ((t == 0) ? 0 : sm[t - 1]);
    #pragma unroll
    for (int i = 0; i < IPT; i++) {
        int idx = base + i;
        if (idx < n) {
            g_rowptr[idx] = run;
            g_cur[idx] = run;
            run += v[i];
        }
    }
}

// ---------------- scatter edges into CSR (col + precomputed norm) ----------------
__global__ void scatter_kernel(const int* __restrict__ src,
                               const int* __restrict__ dst,
                               const float* __restrict__ ew, int E, int n) {
    int e = blockIdx.x * blockDim.x + threadIdx.x;
    if (e >= E) return;
    int s = src[e];
    int d = dst[e];
    if ((unsigned)s >= (unsigned)n || (unsigned)d >= (unsigned)n) return;
    int pos = atomicAdd(&g_cur[d], 1);
    g_col[pos] = s;
    g_val[pos] = g_dinv[s] * ew[e] * g_dinv[d];
}

// ---------------- GEMM: g_hh(fp16) = X @ W  (K=128, BK=16, FFMA2) ----------------
template <int FOUT>
__global__ void gemm_kernel(const float* __restrict__ Xext,
                            const float* __restrict__ W,
                            int n, int useExt) {
    constexpr int K = KDIM, BK = 16, BM = 128, XS = BM + 4;
    constexpr int CG = FOUT / 4;          // 32 (F=128) or 16 (F=64)
    constexpr int NRG = 256 / CG;         // 8 or 16
    constexpr int RPT = BM / NRG;         // 16 or 8
    constexpr int NP = RPT / 2;           // row pairs per thread
    __shared__ float Ws[BK * FOUT];
    __shared__ float Xs[BK * XS];

    const float* X = useExt ? Xext : g_act;
    const int t = threadIdx.x;
    const int rowBase = blockIdx.x * BM;
    const int cg = t % CG, rg = t / CG;
    const int c0 = cg * 4, r0 = rg * RPT;

    unsigned long long acc2[NP][4];
    #pragma unroll
    for (int p = 0; p < NP; p++)
        #pragma unroll
        for (int c = 0; c < 4; c++) acc2[p][c] = 0ull;

    for (int kc = 0; kc < K; kc += BK) {
        #pragma unroll
        for (int i = t; i < BK * FOUT / 4; i += 256) {
            int kk = i / (FOUT / 4), cc = i % (FOUT / 4);
            ((float4*)Ws)[i] =
                ((const float4*)(W + (size_t)(kc + kk) * FOUT))[cc];
        }
        #pragma unroll
        for (int p = 0; p < 2; p++) {
            int idx = p * 256 + t;          // 0..511
            int row = idx >> 2;             // 0..127
            int q = idx & 3;                // float4 within BK=16
            int grow = rowBase + row;
            float4 v = make_float4(0.f, 0.f, 0.f, 0.f);
            if (grow < n) v = *(const float4*)(X + (size_t)grow * K + kc + q * 4);
            Xs[(q * 4 + 0) * XS + row] = v.x;
            Xs[(q * 4 + 1) * XS + row] = v.y;
            Xs[(q * 4 + 2) * XS + row] = v.z;
            Xs[(q * 4 + 3) * XS + row] = v.w;
        }
        __syncthreads();

        #pragma unroll
        for (int k = 0; k < BK; k++) {
            float4 wv = *(const float4*)&Ws[k * FOUT + c0];
            unsigned long long wp0 = pk2(wv.x), wp1 = pk2(wv.y),
                               wp2 = pk2(wv.z), wp3 = pk2(wv.w);
            #pragma unroll
            for (int pq = 0; pq < NP / 2; pq++) {
                ulonglong2 xp = *(const ulonglong2*)&Xs[k * XS + r0 + pq * 4];
                fma2(acc2[pq * 2 + 0][0], xp.x, wp0);
                fma2(acc2[pq * 2 + 0][1], xp.x, wp1);
                fma2(acc2[pq * 2 + 0][2], xp.x, wp2);
                fma2(acc2[pq * 2 + 0][3], xp.x, wp3);
                fma2(acc2[pq * 2 + 1][0], xp.y, wp0);
                fma2(acc2[pq * 2 + 1][1], xp.y, wp1);
                fma2(acc2[pq * 2 + 1][2], xp.y, wp2);
                fma2(acc2[pq * 2 + 1][3], xp.y, wp3);
            }
        }
        __syncthreads();
    }

    #pragma unroll
    for (int p = 0; p < NP; p++) {
        float2 u0 = upk(acc2[p][0]), u1 = upk(acc2[p][1]),
               u2 = upk(acc2[p][2]), u3 = upk(acc2[p][3]);
        int rowA = rowBase + r0 + 2 * p;
        int rowB = rowA + 1;
        if (rowA < n) {
            half2x2 ha;
            ha.a = __floats2half2_rn(u0.x, u1.x);
            ha.b = __floats2half2_rn(u2.x, u3.x);
            *(half2x2*)(g_hh + (size_t)rowA * FOUT + c0) = ha;
        }
        if (rowB < n) {
            half2x2 hb;
            hb.a = __floats2half2_rn(u0.y, u1.y);
            hb.b = __floats2half2_rn(u2.y, u3.y);
            *(half2x2*)(g_hh + (size_t)rowB * FOUT + c0) = hb;
        }
    }
}

// ------- fused aggregate + bias + relu (F=128), warp per node -------
// All feature reads (self-loop + neighbors) from fp16 g_hh; fp32 accumulation.
__global__ void agg_relu_kernel(const float* __restrict__ b, int n) {
    int w = (blockIdx.x * blockDim.x + threadIdx.x) >> 5;
    int lane = threadIdx.x & 31;
    if (w >= n) return;

    float di = g_dinv[w];
    float sv = di * di;
    half2x2 hq = *(const half2x2*)(g_hh + (size_t)w * 128 + lane * 4);
    float2 h0 = __half22float2(hq.a), h1 = __half22float2(hq.b);
    float4 acc = make_float4(h0.x * sv, h0.y * sv, h1.x * sv, h1.y * sv);

    int j = g_rowptr[w], end = g_rowptr[w + 1];
    for (; j + 4 <= end; j += 4) {
        int c0 = g_col[j], c1 = g_col[j + 1], c2 = g_col[j + 2], c3 = g_col[j + 3];
        float v0 = g_val[j], v1 = g_val[j + 1], v2 = g_val[j + 2], v3 = g_val[j + 3];
        half2x2 q0 = *(const half2x2*)(g_hh + (size_t)c0 * 128 + lane * 4);
        half2x2 q1 = *(const half2x2*)(g_hh + (size_t)c1 * 128 + lane * 4);
        half2x2 q2 = *(const half2x2*)(g_hh + (size_t)c2 * 128 + lane * 4);
        half2x2 q3 = *(const half2x2*)(g_hh + (size_t)c3 * 128 + lane * 4);
        float2 a0 = __half22float2(q0.a), b0 = __half22float2(q0.b);
        float2 a1 = __half22float2(q1.a), b1v = __half22float2(q1.b);
        float2 a2 = __half22float2(q2.a), b2v = __half22float2(q2.b);
        float2 a3 = __half22float2(q3.a), b3v = __half22float2(q3.b);
        acc.x += v0 * a0.x + v1 * a1.x + v2 * a2.x + v3 * a3.x;
        acc.y += v0 * a0.y + v1 * a1.y + v2 * a2.y + v3 * a3.y;
        acc.z += v0 * b0.x + v1 * b1v.x + v2 * b2v.x + v3 * b3v.x;
        acc.w += v0 * b0.y + v1 * b1v.y + v2 * b2v.y + v3 * b3v.y;
    }
    for (; j < end; j++) {
        int c0 = g_col[j];
        float v0 = g_val[j];
        half2x2 q0 = *(const half2x2*)(g_hh + (size_t)c0 * 128 + lane * 4);
        float2 a0 = __half22float2(q0.a), b0 = __half22float2(q0.b);
        acc.x += v0 * a0.x; acc.y += v0 * a0.y;
        acc.z += v0 * b0.x; acc.w += v0 * b0.y;
    }

    float4 bb = *(const float4*)(b + lane * 4);
    acc.x = fmaxf(acc.x + bb.x, 0.f);
    acc.y = fmaxf(acc.y + bb.y, 0.f);
    acc.z = fmaxf(acc.z + bb.z, 0.f);
    acc.w = fmaxf(acc.w + bb.w, 0.f);
    *(float4*)(g_act + (size_t)w * 128 + lane * 4) = acc;
}

// ------- fused aggregate + bias + log_softmax (F=64), warp per node -------
__global__ void agg_lsm_kernel(const float* __restrict__ b,
                               float* __restrict__ out, int n) {
    int w = (blockIdx.x * blockDim.x + threadIdx.x) >> 5;
    int lane = threadIdx.x & 31;
    if (w >= n) return;

    float di = g_dinv[w];
    float sv = di * di;
    __half2 hq = *(const __half2*)(g_hh + (size_t)w * 64 + lane * 2);
    float2 hs = __half22float2(hq);
    float2 acc = make_float2(hs.x * sv, hs.y * sv);

    int j = g_rowptr[w], end = g_rowptr[w + 1];
    for (; j + 4 <= end; j += 4) {
        int c0 = g_col[j], c1 = g_col[j + 1], c2 = g_col[j + 2], c3 = g_col[j + 3];
        float v0 = g_val[j], v1 = g_val[j + 1], v2 = g_val[j + 2], v3 = g_val[j + 3];
        __half2 u0 = *(const __half2*)(g_hh + (size_t)c0 * 64 + lane * 2);
        __half2 u1 = *(const __half2*)(g_hh + (size_t)c1 * 64 + lane * 2);
        __half2 u2 = *(const __half2*)(g_hh + (size_t)c2 * 64 + lane * 2);
        __half2 u3 = *(const __half2*)(g_hh + (size_t)c3 * 64 + lane * 2);
        float2 x0 = __half22float2(u0);
        float2 x1 = __half22float2(u1);
        float2 x2 = __half22float2(u2);
        float2 x3 = __half22float2(u3);
        acc.x += v0 * x0.x + v1 * x1.x + v2 * x2.x + v3 * x3.x;
        acc.y += v0 * x0.y + v1 * x1.y + v2 * x2.y + v3 * x3.y;
    }
    for (; j < end; j++) {
        int c0 = g_col[j];
        float v0 = g_val[j];
        __half2 u0 = *(const __half2*)(g_hh + (size_t)c0 * 64 + lane * 2);
        float2 x0 = __half22float2(u0);
        acc.x += v0 * x0.x; acc.y += v0 * x0.y;
    }

    float v0 = acc.x + b[lane * 2];
    float v1 = acc.y + b[lane * 2 + 1];

    float m = fmaxf(v0, v1);
    #pragma unroll
    for (int o = 16; o > 0; o >>= 1)
        m = fmaxf(m, __shfl_xor_sync(0xffffffffu, m, o));
    float s = expf(v0 - m) + expf(v1 - m);
    #pragma unroll
    for (int o = 16; o > 0; o >>= 1)
        s += __shfl_xor_sync(0xffffffffu, s, o);
    float lse = m + logf(s);

    *(float2*)(out + (size_t)w * 64 + lane * 2) = make_float2(v0 - lse, v1 - lse);
}

// ---------------- launch ----------------
static inline int cdiv(int a, int b) { return (a + b - 1) / b; }

extern "C" void kernel_launch(void* const* d_in, const int* in_sizes, int n_in,
                              void* d_out, int out_size) {
    const float* x = (const float*)d_in[0];
    const int* ei = (const int*)d_in[1];      // int32 edge_index [2, E]
    const float* ew = (const float*)d_in[2];
    const float* W1 = (const float*)d_in[3];
    const float* b1 = (const float*)d_in[4];
    const float* W2 = (const float*)d_in[5];
    const float* b2 = (const float*)d_in[6];
    const float* W3 = (const float*)d_in[7];
    const float* b3 = (const float*)d_in[8];
    float* outp = (float*)d_out;

    const int n = in_sizes[0] / 128;
    const int E = in_sizes[2];
    const int* srcI = ei;
    const int* dstI = ei + E;
    const int nblk = cdiv(n, SCAN_ITEMS);

    // ---- gcn_norm + CSR build (sequential) ----
    deg_init_kernel<<<cdiv(n, 256), 256>>>(n);
    deg_acc_kernel<<<cdiv(E, 256), 256>>>(dstI, ew, E, n);
    dinv_kernel<<<cdiv(n, 256), 256>>>(n);
    scan_partial_kernel<<<nblk, 256>>>(n);
    scan_blocks_kernel<<<1, 128>>>(nblk, n);
    scan_final_kernel<<<nblk, 256>>>(n);
    scatter_kernel<<<cdiv(E, 256), 256>>>(srcI, dstI, ew, E, n);

    // ---- layer 1: 128 -> 128, relu ----
    gemm_kernel<128><<<cdiv(n, 128), 256>>>(x, W1, n, 1);
    agg_relu_kernel<<<cdiv(n * 32, 256), 256>>>(b1, n);

    // ---- layer 2: 128 -> 128, relu ----
    gemm_kernel<128><<<cdiv(n, 128), 256>>>(x, W2, n, 0);
    agg_relu_kernel<<<cdiv(n * 32, 256), 256>>>(b2, n);

    // ---- layer 3: 128 -> 64, log_softmax ----
    gemm_kernel<64><<<cdiv(n, 128), 256>>>(x, W3, n, 0);
    agg_lsm_kernel<<<cdiv(n * 32, 256), 256>>>(b3, outp, n);
}